// round 8
// baseline (speedup 1.0000x reference)
#include <cuda_runtime.h>
#include <cuda_bf16.h>

// Embedding gather: out[n, :] = embeddings[inputs[n], :]
// N = 16384 rows, EMB = 128 floats = 32 float4 per row.
//
// Warp-cooperative variant: each warp handles 4 consecutive rows.
//   - lanes 0-3 fetch the 4 indices in ONE coalesced LDG (16B/warp)
//   - __shfl_sync broadcasts each index (26 cyc, off the memory chain)
//   - 4 independent LDG.128 gathers per thread, then 4 coalesced stores
// Chain: 1 idx load -> shfl -> 4 parallel gathers  (vs 2 serial load pairs before)
// Grid: 512 blocks x 256 threads = 4096 warps x 4 rows = 16384 rows. Single wave.

#define N_ROWS   16384
#define EMB_F4   32                  // float4 per row
#define THREADS  256
#define ROWS_PER_WARP 4
#define WARPS_TOTAL   (N_ROWS / ROWS_PER_WARP)        // 4096
#define NBLOCKS       (WARPS_TOTAL / (THREADS / 32))  // 512

__global__ __launch_bounds__(THREADS)
void onehot_embed_gather_shfl(const int* __restrict__ idx,
                              const float4* __restrict__ emb,   // [VOCAB, 32]
                              float4* __restrict__ out)          // [N, 32]
{
    const int warp = (blockIdx.x * THREADS + threadIdx.x) >> 5;
    const int lane = threadIdx.x & 31;
    const int row0 = warp * ROWS_PER_WARP;

    // One coalesced index load per warp: lanes 0-3 carry the 4 row indices.
    int my_idx = 0;
    if (lane < ROWS_PER_WARP) my_idx = __ldg(&idx[row0 + lane]);

    // Broadcast indices; all 4 gathers depend on a single memory op.
    int e[ROWS_PER_WARP];
    #pragma unroll
    for (int r = 0; r < ROWS_PER_WARP; r++)
        e[r] = __shfl_sync(0xFFFFFFFFu, my_idx, r);

    // 4 independent 16B gather loads in flight.
    float4 v[ROWS_PER_WARP];
    #pragma unroll
    for (int r = 0; r < ROWS_PER_WARP; r++)
        v[r] = __ldg(&emb[(long long)e[r] * EMB_F4 + lane]);

    // Coalesced stores (each row = one full warp-wide 512B store).
    #pragma unroll
    for (int r = 0; r < ROWS_PER_WARP; r++)
        out[(row0 + r) * EMB_F4 + lane] = v[r];
}

extern "C" void kernel_launch(void* const* d_in, const int* in_sizes, int n_in,
                              void* d_out, int out_size)
{
    const int*    idx = (const int*)   d_in[0];   // int32 [16384]
    const float4* emb = (const float4*)d_in[1];   // float32 [32000,128]
    float4*       out = (float4*)      d_out;     // float32 [16384,128]

    onehot_embed_gather_shfl<<<NBLOCKS, THREADS>>>(idx, emb, out);
}